// round 11
// baseline (speedup 1.0000x reference)
#include <cuda_runtime.h>
#include <cuda_fp16.h>
#include <stdint.h>
#include <math.h>

// Problem constants
#define BB 8192
#define NN 2048

// GEMM tiling: CTA 256x128, 8 warps in 4x2, warp tile 64x64 (f16 acc), BK=64
#define BM 256
#define BN 128
#define BK 64
#define GRID_B (BB / BM)          // 32
#define GRID_N (NN / BN)          // 16
#define NBLK   (GRID_B * GRID_N)  // 512

#define A_BYTES     (BM * BK * 2)            // 32768
#define B_BYTES     (BN * BK * 2)            // 16384
#define STAGE_BYTES (A_BYTES + B_BYTES)      // 49152
#define SMEM_BYTES  (2 * STAGE_BYTES)        // 98304 (2-stage, 2 CTAs/SM)

__device__ float g_w[NN];
__device__ __half g_xh[(size_t)BB * NN];   // x in fp16 (32 MB)
__device__ __half g_th[(size_t)NN * NN];   // scale * Toeplitz(w), fp16 (8 MB)
__device__ float g_part[NBLK];

// ---------------- helpers ----------------
__device__ __forceinline__ uint32_t smem_u32(const void* p) {
    return (uint32_t)__cvta_generic_to_shared(p);
}
__device__ __forceinline__ uint32_t swz128(uint32_t off) {
    return off ^ ((off >> 3) & 0x70);
}
__device__ __forceinline__ void cp16(uint32_t saddr, const void* g) {
    asm volatile("cp.async.cg.shared.global [%0], [%1], 16;" :: "r"(saddr), "l"(g));
}
#define CP_COMMIT() asm volatile("cp.async.commit_group;" ::: "memory")
#define CP_WAIT(n)  asm volatile("cp.async.wait_group %0;" :: "n"(n) : "memory")

__device__ __forceinline__ void ldm_x4(uint32_t& r0, uint32_t& r1, uint32_t& r2,
                                       uint32_t& r3, uint32_t addr) {
    asm volatile("ldmatrix.sync.aligned.m8n8.x4.shared.b16 {%0,%1,%2,%3}, [%4];"
                 : "=r"(r0), "=r"(r1), "=r"(r2), "=r"(r3) : "r"(addr));
}
// f16 inputs, f16 accumulators (2 b32 regs hold 4 halves)
__device__ __forceinline__ void mma16816h(uint32_t* c, const uint32_t* a, const uint32_t* b) {
    asm volatile("mma.sync.aligned.m16n8k16.row.col.f16.f16.f16.f16 "
                 "{%0,%1}, {%2,%3,%4,%5}, {%6,%7}, {%0,%1};"
                 : "+r"(c[0]), "+r"(c[1])
                 : "r"(a[0]), "r"(a[1]), "r"(a[2]), "r"(a[3]), "r"(b[0]), "r"(b[1]));
}

// ---------------------------------------------------------------------------
// GL weights (parallel chunked cumprod)
// ---------------------------------------------------------------------------
__global__ void gl_weights_kernel() {
    __shared__ float sp[256];
    const int t = threadIdx.x;
    float f[8];
    float p = 1.0f;
#pragma unroll
    for (int r = 0; r < 8; ++r) {
        const int k = t * 8 + 1 + r;
        f[r] = ((float)k - 1.5f) / (float)k;
        p *= f[r];
    }
    sp[t] = p;
    __syncthreads();
    for (int s = 1; s < 256; s <<= 1) {
        float v = (t >= s) ? sp[t - s] : 1.0f;
        __syncthreads();
        sp[t] *= v;
        __syncthreads();
    }
    float w = (t == 0) ? 1.0f : sp[t - 1];
    g_w[t * 8] = w;
#pragma unroll
    for (int r = 0; r < 7; ++r) {
        w *= f[r];
        g_w[t * 8 + r + 1] = w;
    }
}

// ---------------------------------------------------------------------------
// x fp32 -> fp16
// ---------------------------------------------------------------------------
__global__ void __launch_bounds__(256) convert_kernel(const float* __restrict__ x) {
    const size_t i = ((size_t)blockIdx.x * 256 + threadIdx.x) * 8;
    const float4 a = *reinterpret_cast<const float4*>(x + i);
    const float4 b = *reinterpret_cast<const float4*>(x + i + 4);
    __half2 o[4];
    o[0] = __floats2half2_rn(a.x, a.y);
    o[1] = __floats2half2_rn(a.z, a.w);
    o[2] = __floats2half2_rn(b.x, b.y);
    o[3] = __floats2half2_rn(b.z, b.w);
    *reinterpret_cast<uint4*>(&g_xh[i]) = *reinterpret_cast<uint4*>(o);
}

// ---------------------------------------------------------------------------
// T[n,k] = (k<=n) ? scale * w[n-k] : 0, fp16 (scale folded in)
// ---------------------------------------------------------------------------
__global__ void __launch_bounds__(256) build_t_kernel() {
    const int n = blockIdx.x;
    const float scale = sqrtf((float)(NN - 1));
    const int k0 = threadIdx.x * 8;
    __half2 o[4];
#pragma unroll
    for (int r = 0; r < 4; ++r) {
        const int ka = k0 + 2 * r, kb = ka + 1;
        const float va = (ka <= n) ? scale * g_w[n - ka] : 0.0f;
        const float vb = (kb <= n) ? scale * g_w[n - kb] : 0.0f;
        o[r] = __floats2half2_rn(va, vb);
    }
    *reinterpret_cast<uint4*>(&g_th[(size_t)n * NN + k0]) = *reinterpret_cast<uint4*>(o);
}

// ---------------------------------------------------------------------------
// fp16 HMMA GEMM (f16 accumulate) + fused MSE partial
// CTA 256x128, 8 warps (4Mx2N), warp tile 64x64, 2-stage, 1 sync/iter
// 128 B LDSM per MMA (operand-minimal); 2 CTAs/SM cover barrier windows
// ---------------------------------------------------------------------------
__device__ __forceinline__ void load_stage(uint32_t sbase, int b0, int n0,
                                           int kt, int tid) {
    const __half* asrc = g_xh + (size_t)b0 * NN + kt * BK;
    const __half* bsrc = g_th + (size_t)n0 * NN + kt * BK;
    // A: 256 rows x 8 chunks(16B) = 2048 chunks / 256 threads = 8 each
#pragma unroll
    for (int i = 0; i < 8; ++i) {
        const int idx = tid + i * 256;
        const int row = idx >> 3;
        const int ch  = idx & 7;
        cp16(sbase + swz128(row * 128 + ch * 16),
             asrc + (size_t)row * NN + ch * 8);
    }
    // B: 128 rows x 8 chunks = 1024 chunks / 256 = 4 each
#pragma unroll
    for (int i = 0; i < 4; ++i) {
        const int idx = tid + i * 256;
        const int row = idx >> 3;
        const int ch  = idx & 7;
        cp16(sbase + A_BYTES + swz128(row * 128 + ch * 16),
             bsrc + (size_t)row * NN + ch * 8);
    }
}

__global__ void __launch_bounds__(256, 2)
gemm_kernel(const float* __restrict__ tgt) {
    extern __shared__ char smem[];
    __shared__ float red[8];
    const uint32_t sb = smem_u32(smem);
    const int tid  = threadIdx.x;
    const int wid  = tid >> 5;
    const int lane = tid & 31;
    const int wm   = wid >> 1;        // 0..3 (M)
    const int wn   = wid & 1;         // 0..1 (N)
    const int n0 = blockIdx.x * BN;
    const int b0 = blockIdx.y * BM;

    uint32_t c[4][8][2];              // f16x2 accumulators (64 regs)
#pragma unroll
    for (int mi = 0; mi < 4; ++mi)
#pragma unroll
        for (int nj = 0; nj < 8; ++nj) { c[mi][nj][0] = 0u; c[mi][nj][1] = 0u; }

    const int KT = n0 / BK + 2;   // triangular skip: k < n0 + BN

    // prologue: stage 0 into slot 0
    load_stage(sb, b0, n0, 0, tid);
    CP_COMMIT();

    // per-thread ldmatrix address components (within a stage)
    const uint32_t a_row = wm * 64 + (lane & 15);                          // + mi*16
    const uint32_t a_kg  = (lane >> 4) * 8;                                // + ks*16
    const uint32_t b_row = wn * 64 + (lane & 7) + ((lane >> 4) & 1) * 8;   // + g*16
    const uint32_t b_kg  = ((lane >> 3) & 1) * 8;                          // + ks*16

    for (int kt = 0; kt < KT; ++kt) {
        CP_WAIT(0);                     // stage kt landed (only group in flight)
        __syncthreads();                // all warps done reading the other slot

        if (kt + 1 < KT) load_stage(sb + ((kt + 1) & 1) * STAGE_BYTES, b0, n0, kt + 1, tid);
        CP_COMMIT();

        const uint32_t cur = sb + (kt & 1) * STAGE_BYTES;
#pragma unroll
        for (int ks = 0; ks < BK / 16; ++ks) {
            uint32_t a[4][4], b[8][2];
#pragma unroll
            for (int mi = 0; mi < 4; ++mi)
                ldm_x4(a[mi][0], a[mi][1], a[mi][2], a[mi][3],
                       cur + swz128((a_row + mi * 16) * 128 + (ks * 16 + a_kg) * 2));
#pragma unroll
            for (int g = 0; g < 4; ++g)
                ldm_x4(b[2 * g][0], b[2 * g][1], b[2 * g + 1][0], b[2 * g + 1][1],
                       cur + A_BYTES +
                       swz128((b_row + g * 16) * 128 + (ks * 16 + b_kg) * 2));
#pragma unroll
            for (int mi = 0; mi < 4; ++mi)
#pragma unroll
                for (int nj = 0; nj < 8; ++nj)
                    mma16816h(c[mi][nj], a[mi], b[nj]);
        }
    }

    // Epilogue: (y - t)^2 partial sums. c[..][0] = row rb+mi*16, cols (cb,cb+1);
    // c[..][1] = row rb+mi*16+8, same cols.
    float lsum = 0.0f;
    const int rb = b0 + wm * 64 + (lane >> 2);
    const int cb = n0 + wn * 64 + (lane & 3) * 2;
#pragma unroll
    for (int mi = 0; mi < 4; ++mi) {
#pragma unroll
        for (int nj = 0; nj < 8; ++nj) {
            const int r = rb + mi * 16;
            const int cc = cb + nj * 8;
            const float2 t0 = *reinterpret_cast<const float2*>(tgt + (size_t)r * NN + cc);
            const float2 t1 = *reinterpret_cast<const float2*>(tgt + (size_t)(r + 8) * NN + cc);
            const float2 y0 = __half22float2(*reinterpret_cast<__half2*>(&c[mi][nj][0]));
            const float2 y1 = __half22float2(*reinterpret_cast<__half2*>(&c[mi][nj][1]));
            const float d0 = y0.x - t0.x;
            const float d1 = y0.y - t0.y;
            const float d2 = y1.x - t1.x;
            const float d3 = y1.y - t1.y;
            lsum += d0 * d0 + d1 * d1 + d2 * d2 + d3 * d3;
        }
    }
#pragma unroll
    for (int s = 16; s > 0; s >>= 1)
        lsum += __shfl_xor_sync(0xFFFFFFFF, lsum, s);
    if (lane == 0) red[wid] = lsum;
    __syncthreads();
    if (tid == 0) {
        float s = 0.0f;
#pragma unroll
        for (int i = 0; i < 8; ++i) s += red[i];
        g_part[blockIdx.y * GRID_N + blockIdx.x] = s;
    }
}

// ---------------------------------------------------------------------------
// Final deterministic reduction (double accumulation)
// ---------------------------------------------------------------------------
__global__ void final_reduce_kernel(float* __restrict__ out) {
    __shared__ double red[256];
    const int t = threadIdx.x;
    double s = 0.0;
    for (int i = t; i < NBLK; i += 256) s += (double)g_part[i];
    red[t] = s;
    __syncthreads();
    for (int st = 128; st > 0; st >>= 1) {
        if (t < st) red[t] += red[t + st];
        __syncthreads();
    }
    if (t == 0) out[0] = (float)(red[0] / ((double)BB * (double)NN));
}

extern "C" void kernel_launch(void* const* d_in, const int* in_sizes, int n_in,
                              void* d_out, int out_size) {
    const float* pred = (const float*)d_in[0];
    const float* tgt  = (const float*)d_in[1];
    float* out = (float*)d_out;

    cudaFuncSetAttribute(gemm_kernel, cudaFuncAttributeMaxDynamicSharedMemorySize,
                         SMEM_BYTES);

    gl_weights_kernel<<<1, 256>>>();
    convert_kernel<<<(BB * NN) / (256 * 8), 256>>>(pred);
    build_t_kernel<<<NN, 256>>>();
    dim3 grid(GRID_N, GRID_B);
    gemm_kernel<<<grid, 256, SMEM_BYTES>>>(tgt);
    final_reduce_kernel<<<1, 256>>>(out);
}

// round 12
// speedup vs baseline: 1.1481x; 1.1481x over previous
#include <cuda_runtime.h>
#include <cuda_fp16.h>
#include <stdint.h>
#include <math.h>

// Problem constants
#define BB 8192
#define NN 2048

// GEMM tiling: CTA 128x128, 8 warps in 4x2, warp tile 32x64, BK=64, 3 stages
#define BM 128
#define BN 128
#define BK 64
#define NSTAGE 3
#define GRID_B (BB / BM)          // 64
#define GRID_N (NN / BN)          // 16
#define NBLK   (GRID_B * GRID_N)  // 1024

#define TILE_BYTES  (BM * BK * 2)            // 16384
#define STAGE_BYTES (2 * TILE_BYTES)         // 32768
#define SMEM_BYTES  (NSTAGE * STAGE_BYTES)   // 98304

__device__ float g_w[NN];
__device__ __half g_xh[(size_t)BB * NN];   // x in fp16 (32 MB)
__device__ __half g_th[(size_t)NN * NN];   // scale * Toeplitz(w), fp16 (8 MB)
__device__ float g_part[NBLK];

// ---------------- helpers ----------------
__device__ __forceinline__ uint32_t smem_u32(const void* p) {
    return (uint32_t)__cvta_generic_to_shared(p);
}
__device__ __forceinline__ uint32_t swz128(uint32_t off) {
    return off ^ ((off >> 3) & 0x70);
}
__device__ __forceinline__ void cp16(uint32_t saddr, const void* g) {
    asm volatile("cp.async.cg.shared.global [%0], [%1], 16;" :: "r"(saddr), "l"(g));
}
#define CP_COMMIT() asm volatile("cp.async.commit_group;" ::: "memory")
#define CP_WAIT(n)  asm volatile("cp.async.wait_group %0;" :: "n"(n) : "memory")

__device__ __forceinline__ void ldm_x4(uint32_t& r0, uint32_t& r1, uint32_t& r2,
                                       uint32_t& r3, uint32_t addr) {
    asm volatile("ldmatrix.sync.aligned.m8n8.x4.shared.b16 {%0,%1,%2,%3}, [%4];"
                 : "=r"(r0), "=r"(r1), "=r"(r2), "=r"(r3) : "r"(addr));
}
// f16 inputs, f16 accumulators. NOT volatile: pure register op, dataflow-only
// deps -> compiler may interleave MMAs with subsequent LDSMs (software pipelining).
__device__ __forceinline__ void mma16816h(uint32_t* c, const uint32_t* a, const uint32_t* b) {
    asm("mma.sync.aligned.m16n8k16.row.col.f16.f16.f16.f16 "
        "{%0,%1}, {%2,%3,%4,%5}, {%6,%7}, {%0,%1};"
        : "+r"(c[0]), "+r"(c[1])
        : "r"(a[0]), "r"(a[1]), "r"(a[2]), "r"(a[3]), "r"(b[0]), "r"(b[1]));
}

// ---------------------------------------------------------------------------
// GL weights (parallel chunked cumprod)
// ---------------------------------------------------------------------------
__global__ void gl_weights_kernel() {
    __shared__ float sp[256];
    const int t = threadIdx.x;
    float f[8];
    float p = 1.0f;
#pragma unroll
    for (int r = 0; r < 8; ++r) {
        const int k = t * 8 + 1 + r;
        f[r] = ((float)k - 1.5f) / (float)k;
        p *= f[r];
    }
    sp[t] = p;
    __syncthreads();
    for (int s = 1; s < 256; s <<= 1) {
        float v = (t >= s) ? sp[t - s] : 1.0f;
        __syncthreads();
        sp[t] *= v;
        __syncthreads();
    }
    float w = (t == 0) ? 1.0f : sp[t - 1];
    g_w[t * 8] = w;
#pragma unroll
    for (int r = 0; r < 7; ++r) {
        w *= f[r];
        g_w[t * 8 + r + 1] = w;
    }
}

// ---------------------------------------------------------------------------
// x fp32 -> fp16
// ---------------------------------------------------------------------------
__global__ void __launch_bounds__(256) convert_kernel(const float* __restrict__ x) {
    const size_t i = ((size_t)blockIdx.x * 256 + threadIdx.x) * 8;
    const float4 a = *reinterpret_cast<const float4*>(x + i);
    const float4 b = *reinterpret_cast<const float4*>(x + i + 4);
    __half2 o[4];
    o[0] = __floats2half2_rn(a.x, a.y);
    o[1] = __floats2half2_rn(a.z, a.w);
    o[2] = __floats2half2_rn(b.x, b.y);
    o[3] = __floats2half2_rn(b.z, b.w);
    *reinterpret_cast<uint4*>(&g_xh[i]) = *reinterpret_cast<uint4*>(o);
}

// ---------------------------------------------------------------------------
// T[n,k] = (k<=n) ? scale * w[n-k] : 0, fp16 (scale folded in)
// ---------------------------------------------------------------------------
__global__ void __launch_bounds__(256) build_t_kernel() {
    const int n = blockIdx.x;
    const float scale = sqrtf((float)(NN - 1));
    const int k0 = threadIdx.x * 8;
    __half2 o[4];
#pragma unroll
    for (int r = 0; r < 4; ++r) {
        const int ka = k0 + 2 * r, kb = ka + 1;
        const float va = (ka <= n) ? scale * g_w[n - ka] : 0.0f;
        const float vb = (kb <= n) ? scale * g_w[n - kb] : 0.0f;
        o[r] = __floats2half2_rn(va, vb);
    }
    *reinterpret_cast<uint4*>(&g_th[(size_t)n * NN + k0]) = *reinterpret_cast<uint4*>(o);
}

// ---------------------------------------------------------------------------
// fp16 HMMA GEMM (f16 accumulate) + fused MSE partial
// CTA 128x128, 8 warps (4Mx2N), warp tile 32x64, 3-stage ring, 1 sync/iter
// ---------------------------------------------------------------------------
__device__ __forceinline__ void load_stage(uint32_t sbase, int b0, int n0,
                                           int kt, int tid) {
    const __half* asrc = g_xh + (size_t)b0 * NN + kt * BK;
    const __half* bsrc = g_th + (size_t)n0 * NN + kt * BK;
#pragma unroll
    for (int i = 0; i < 4; ++i) {
        const int idx = tid + i * 256;
        const int row = idx >> 3;
        const int ch  = idx & 7;
        const uint32_t off = swz128(row * 128 + ch * 16);
        cp16(sbase + off,              asrc + (size_t)row * NN + ch * 8);
        cp16(sbase + TILE_BYTES + off, bsrc + (size_t)row * NN + ch * 8);
    }
}

__global__ void __launch_bounds__(256, 2)
gemm_kernel(const float* __restrict__ tgt) {
    extern __shared__ char smem[];
    __shared__ float red[8];
    const uint32_t sb = smem_u32(smem);
    const int tid  = threadIdx.x;
    const int wid  = tid >> 5;
    const int lane = tid & 31;
    const int wm   = wid >> 1;        // 0..3 (M)
    const int wn   = wid & 1;         // 0..1 (N)
    const int n0 = blockIdx.x * BN;
    const int b0 = blockIdx.y * BM;

    uint32_t c[2][8][2];              // f16x2 accumulators
#pragma unroll
    for (int mi = 0; mi < 2; ++mi)
#pragma unroll
        for (int nj = 0; nj < 8; ++nj) { c[mi][nj][0] = 0u; c[mi][nj][1] = 0u; }

    const int KT = n0 / BK + 2;   // triangular skip: k < n0 + BN

    // prologue: stages 0 .. NSTAGE-2
#pragma unroll
    for (int s = 0; s < NSTAGE - 1; ++s) {
        if (s < KT) load_stage(sb + s * STAGE_BYTES, b0, n0, s, tid);
        CP_COMMIT();
    }

    // per-thread ldmatrix address components (within a stage)
    const uint32_t a_row = wm * 32 + (lane & 15);                          // + mi*16
    const uint32_t a_kg  = (lane >> 4) * 8;                                // + ks*16
    const uint32_t b_row = wn * 64 + (lane & 7) + ((lane >> 4) & 1) * 8;   // + g*16
    const uint32_t b_kg  = ((lane >> 3) & 1) * 8;                          // + ks*16

    int slot = 0, nslot = NSTAGE - 1;
    for (int kt = 0; kt < KT; ++kt) {
        CP_WAIT(NSTAGE - 2);            // stage kt ready
        __syncthreads();                // all warps done reading slot nslot

        const int kn = kt + NSTAGE - 1;
        if (kn < KT) load_stage(sb + nslot * STAGE_BYTES, b0, n0, kn, tid);
        CP_COMMIT();

        const uint32_t cur = sb + slot * STAGE_BYTES;
#pragma unroll
        for (int ks = 0; ks < BK / 16; ++ks) {
            uint32_t a[2][4], b[8][2];
#pragma unroll
            for (int mi = 0; mi < 2; ++mi)
                ldm_x4(a[mi][0], a[mi][1], a[mi][2], a[mi][3],
                       cur + swz128((a_row + mi * 16) * 128 + (ks * 16 + a_kg) * 2));
#pragma unroll
            for (int g = 0; g < 4; ++g)
                ldm_x4(b[2 * g][0], b[2 * g][1], b[2 * g + 1][0], b[2 * g + 1][1],
                       cur + TILE_BYTES +
                       swz128((b_row + g * 16) * 128 + (ks * 16 + b_kg) * 2));
#pragma unroll
            for (int mi = 0; mi < 2; ++mi)
#pragma unroll
                for (int nj = 0; nj < 8; ++nj)
                    mma16816h(c[mi][nj], a[mi], b[nj]);
        }
        slot = (slot + 1 == NSTAGE) ? 0 : slot + 1;
        nslot = (nslot + 1 == NSTAGE) ? 0 : nslot + 1;
    }

    // Epilogue: (y - t)^2 partial sums. c[..][0] = row rb, cols (cb,cb+1);
    // c[..][1] = row rb+8, same cols.
    float lsum = 0.0f;
    const int rb = b0 + wm * 32 + (lane >> 2);
    const int cb = n0 + wn * 64 + (lane & 3) * 2;
#pragma unroll
    for (int mi = 0; mi < 2; ++mi) {
#pragma unroll
        for (int nj = 0; nj < 8; ++nj) {
            const int r = rb + mi * 16;
            const int cc = cb + nj * 8;
            const float2 t0 = *reinterpret_cast<const float2*>(tgt + (size_t)r * NN + cc);
            const float2 t1 = *reinterpret_cast<const float2*>(tgt + (size_t)(r + 8) * NN + cc);
            const float2 y0 = __half22float2(*reinterpret_cast<__half2*>(&c[mi][nj][0]));
            const float2 y1 = __half22float2(*reinterpret_cast<__half2*>(&c[mi][nj][1]));
            const float d0 = y0.x - t0.x;
            const float d1 = y0.y - t0.y;
            const float d2 = y1.x - t1.x;
            const float d3 = y1.y - t1.y;
            lsum += d0 * d0 + d1 * d1 + d2 * d2 + d3 * d3;
        }
    }
#pragma unroll
    for (int s = 16; s > 0; s >>= 1)
        lsum += __shfl_xor_sync(0xFFFFFFFF, lsum, s);
    if (lane == 0) red[wid] = lsum;
    __syncthreads();
    if (tid == 0) {
        float s = 0.0f;
#pragma unroll
        for (int i = 0; i < 8; ++i) s += red[i];
        g_part[blockIdx.y * GRID_N + blockIdx.x] = s;
    }
}

// ---------------------------------------------------------------------------
// Final deterministic reduction (double accumulation)
// ---------------------------------------------------------------------------
__global__ void final_reduce_kernel(float* __restrict__ out) {
    __shared__ double red[256];
    const int t = threadIdx.x;
    double s = 0.0;
    for (int i = t; i < NBLK; i += 256) s += (double)g_part[i];
    red[t] = s;
    __syncthreads();
    for (int st = 128; st > 0; st >>= 1) {
        if (t < st) red[t] += red[t + st];
        __syncthreads();
    }
    if (t == 0) out[0] = (float)(red[0] / ((double)BB * (double)NN));
}

extern "C" void kernel_launch(void* const* d_in, const int* in_sizes, int n_in,
                              void* d_out, int out_size) {
    const float* pred = (const float*)d_in[0];
    const float* tgt  = (const float*)d_in[1];
    float* out = (float*)d_out;

    cudaFuncSetAttribute(gemm_kernel, cudaFuncAttributeMaxDynamicSharedMemorySize,
                         SMEM_BYTES);

    gl_weights_kernel<<<1, 256>>>();
    convert_kernel<<<(BB * NN) / (256 * 8), 256>>>(pred);
    build_t_kernel<<<NN, 256>>>();
    dim3 grid(GRID_N, GRID_B);
    gemm_kernel<<<grid, 256, SMEM_BYTES>>>(tgt);
    final_reduce_kernel<<<1, 256>>>(out);
}